// round 5
// baseline (speedup 1.0000x reference)
#include <cuda_runtime.h>
#include <cuda_bf16.h>

// Problem constants
#define NXS    41
#define GTOT   68921          // 41^3
#define NX2    1681           // 41^2
#define WORDS  2154           // ceil(GTOT/32)
#define WPAD   2156           // padded word count (multiple of 4)
#define CHUNKS 539            // ceil(GTOT/128)
#define FULLCH 538            // full 128-voxel chunks
#define KPK    4
#define NEGV   (-1.0e9f)
#define VTH    (-1.0e8f)
#define NPAIR  512            // B*N*C = 1*128*4
#define CPART  135            // chunks per scan-CTA (4 parts: 135,135,135,134)

// Sphere mask as uint4-aligned words (2160 words incl. zero padding)
__device__ uint4 g_sphere_mask4[540];
// Per-pair per-chunk maxima (monotone uint keys), padded stride
__device__ unsigned int g_ckey[NPAIR][544];

// ---------------------------------------------------------------------------
// Kernel 1: sphere mask bits from grid_xyz with numpy-identical fp32 ops.
// Grid covers 2160 words (69120 threads); out-of-range lanes produce 0 bits.
// ---------------------------------------------------------------------------
__global__ __launch_bounds__(256) void init_sphere_kernel(const float* __restrict__ grid_xyz)
{
    int g = blockIdx.x * 256 + threadIdx.x;
    bool ok = false;
    if (g < GTOT) {
        float x = grid_xyz[3 * g + 0];
        float y = grid_xyz[3 * g + 1];
        float z = grid_xyz[3 * g + 2];
        float s = __fadd_rn(__fadd_rn(__fmul_rn(x, x), __fmul_rn(y, y)), __fmul_rn(z, z));
        ok = (__fsqrt_rn(s) <= 6.0f);
    }
    unsigned int ballot = __ballot_sync(0xffffffffu, ok);
    if ((threadIdx.x & 31) == 0) {
        int w = g >> 5;
        if (w < 2160) ((unsigned int*)g_sphere_mask4)[w] = ballot;
    }
}

// order-preserving float->uint key; 0 reserved as "masked" (below all real keys)
__device__ __forceinline__ unsigned int f2key(float v)
{
    int i = __float_as_int(v);
    return (unsigned int)(i ^ ((i >> 31) | 0x80000000));
}
__device__ __forceinline__ float key2f(unsigned int k)
{
    int i = (k & 0x80000000u) ? (int)(k ^ 0x80000000u) : (int)~k;
    return __int_as_float(i);
}

// ---------------------------------------------------------------------------
// Kernel 2: streaming masked chunk-max scan. 4 CTAs per pair, no smem/syncs.
// ---------------------------------------------------------------------------
__global__ __launch_bounds__(256) void scan_kernel(const float* __restrict__ density)
{
    const int part  = blockIdx.x & 3;
    const int pair  = blockIdx.x >> 2;
    const int start = part * CPART;
    const int end   = min(start + CPART, CHUNKS);
    const int lane  = threadIdx.x & 31;
    const int wid   = threadIdx.x >> 5;
    const float* __restrict__ dens = density + (size_t)pair * GTOT;
    unsigned int* __restrict__ ck = g_ckey[pair];

    for (int cb = start + wid * 4; cb < end; cb += 32) {
        // uniform mask loads (LDG.128 each, broadcast across warp)
        uint4 m[4];
        #pragma unroll
        for (int b = 0; b < 4; ++b) {
            int c = min(cb + b, end - 1);
            m[b] = g_sphere_mask4[c];
        }
        unsigned int any =
            (m[0].x | m[0].y | m[0].z | m[0].w) |
            (m[1].x | m[1].y | m[1].z | m[1].w) |
            (m[2].x | m[2].y | m[2].z | m[2].w) |
            (m[3].x | m[3].y | m[3].z | m[3].w);
        if (any == 0u) {                 // warp-uniform: whole 512-voxel batch masked
            if (lane == 0) {
                #pragma unroll
                for (int b = 0; b < 4; ++b) {
                    int c = cb + b;
                    if (c < end) ck[c] = 0u;
                }
            }
            continue;
        }
        // 16 batched density loads (MLP=16 per warp)
        float vv[4][4];
        #pragma unroll
        for (int b = 0; b < 4; ++b) {
            int c = min(cb + b, end - 1);
            #pragma unroll
            for (int u = 0; u < 4; ++u)
                vv[b][u] = __ldg(&dens[min(c * 128 + u * 32 + lane, GTOT - 1)]);
        }
        #pragma unroll
        for (int b = 0; b < 4; ++b) {
            unsigned int mw0 = m[b].x, mw1 = m[b].y, mw2 = m[b].z, mw3 = m[b].w;
            unsigned int best = 0;
            unsigned int keep;
            keep = (unsigned int)(((int)(mw0 << (31 - lane))) >> 31);
            best = max(best, f2key(vv[b][0]) & keep);
            keep = (unsigned int)(((int)(mw1 << (31 - lane))) >> 31);
            best = max(best, f2key(vv[b][1]) & keep);
            keep = (unsigned int)(((int)(mw2 << (31 - lane))) >> 31);
            best = max(best, f2key(vv[b][2]) & keep);
            keep = (unsigned int)(((int)(mw3 << (31 - lane))) >> 31);
            best = max(best, f2key(vv[b][3]) & keep);
            unsigned int r = __reduce_max_sync(0xffffffffu, best);
            int c = cb + b;
            if (lane == 0 && c < end) ck[c] = r;
        }
    }
}

// ---------------------------------------------------------------------------
// Kernel 3: per-(n,c) iterative argmax + Chebyshev NMS using chunk-max table.
// ---------------------------------------------------------------------------
__global__ __launch_bounds__(256) void pick_kernel(
    const float* __restrict__ density,   // [512, G]
    const float* __restrict__ grid_xyz,  // [G, 3]
    const float* __restrict__ Rmats,     // [128, 3, 3]
    const float* __restrict__ tpos,      // [128, 3]
    const float* __restrict__ node_mask, // [128]
    float* __restrict__ out)             // 16384 floats
{
    __shared__ unsigned int smask[WPAD];    // live bits (padded tail = 0)
    __shared__ unsigned int ckey[CHUNKS];   // per-chunk max (monotone key)
    __shared__ unsigned int swk[8];
    __shared__ int          sww[8];
    __shared__ float pk_score[KPK];
    __shared__ int   pk_idx[KPK];
    __shared__ int   pk_valid[KPK];
    __shared__ int   cur_i, cur_j, cur_k, cur_valid;
    __shared__ int   wlist[128];
    __shared__ int   wcount;

    const int pair = blockIdx.x;            // n*4 + c
    const int tid  = threadIdx.x;
    const int lane = tid & 31;
    const int wid  = tid >> 5;
    const float* __restrict__ dens = density + (size_t)pair * GTOT;
    const unsigned int* __restrict__ gsm = (const unsigned int*)g_sphere_mask4;

    for (int w = tid; w < WPAD; w += 256) smask[w] = gsm[w];
    for (int c = tid; c < CHUNKS; c += 256) ckey[c] = g_ckey[pair][c];
    __syncthreads();

    for (int t = 0; t < KPK; ++t) {
        // ---- argmax over per-chunk maxima ----
        unsigned int bk = 0;
        int bc = 0x7FFFFFFF;
        for (int c = tid; c < CHUNKS; c += 256) {
            unsigned int k = ckey[c];
            if (k > bk) { bk = k; bc = c; }     // ascending: lowest c on ties
        }
        unsigned int wm = __reduce_max_sync(0xffffffffu, bk);
        int cand = (bk == wm) ? bc : 0x7FFFFFFF;
        int wmin = (int)__reduce_min_sync(0xffffffffu, (unsigned int)cand);
        if (lane == 0) { swk[wid] = wm; sww[wid] = wmin; }
        __syncthreads();
        if (wid == 0) {
            unsigned int k8 = (lane < 8) ? swk[lane] : 0u;
            int w8 = (lane < 8) ? sww[lane] : 0x7FFFFFFF;
            unsigned int fm = __reduce_max_sync(0xffffffffu, k8);
            int c8 = (k8 == fm) ? w8 : 0x7FFFFFFF;
            int fc = (int)__reduce_min_sync(0xffffffffu, (unsigned int)c8);
            // lazy in-chunk argmax (lowest g on ties)
            unsigned int bestk = 0;
            int bestg = 0x7FFFFFFF;
            #pragma unroll
            for (int u = 0; u < 4; ++u) {
                int g = fc * 128 + u * 32 + lane;
                int gc = min(g, GTOT - 1);
                unsigned int keep = (unsigned int)(((int)(smask[fc * 4 + u] << (31 - lane))) >> 31);
                unsigned int key = f2key(__ldg(&dens[gc])) & keep;
                if (key > bestk) { bestk = key; bestg = g; }  // ascending u: lowest g
            }
            int cg = (bestk == fm) ? bestg : 0x7FFFFFFF;
            int gi = (int)__reduce_min_sync(0xffffffffu, (unsigned int)cg);
            if (lane == 0) {
                float sc = key2f(fm);
                int valid = (sc > VTH) ? 1 : 0;
                pk_score[t] = sc;
                pk_idx[t]   = gi;
                pk_valid[t] = valid;
                cur_valid = valid;
                cur_i = gi / NX2;
                cur_j = (gi / NXS) % NXS;
                cur_k = gi % NXS;
                wcount = 0;
            }
        }
        __syncthreads();

        if (t < KPK - 1 && cur_valid) {
            // ---- clear bits in <=7x7x7 Chebyshev cube; collect touched chunks ----
            int i0 = max(cur_i - 3, 0), i1 = min(cur_i + 3, NXS - 1);
            int j0 = max(cur_j - 3, 0), j1 = min(cur_j + 3, NXS - 1);
            int k0 = max(cur_k - 3, 0), k1 = min(cur_k + 3, NXS - 1);
            int nj = j1 - j0 + 1;
            int nrows = (i1 - i0 + 1) * nj;
            // rows are >=35 bits apart -> never share a 32-bit word -> no races
            if (tid < nrows) {
                int i = i0 + tid / nj;
                int j = j0 + tid % nj;
                int gb = i * NX2 + j * NXS + k0;
                int ge = gb + (k1 - k0);
                int w0 = gb >> 5, w1 = ge >> 5;
                unsigned int b0 = (unsigned int)(gb & 31);
                unsigned int b1 = (unsigned int)(ge & 31);
                unsigned int hi = (b1 == 31u) ? 0xffffffffu : ((1u << (b1 + 1)) - 1u);
                int slot;
                if (w0 == w1) {
                    unsigned int m = hi & ~((1u << b0) - 1u);
                    smask[w0] &= ~m;
                    slot = atomicAdd(&wcount, 1);
                    wlist[slot] = w0 >> 2;
                } else {
                    smask[w0] &= ((1u << b0) - 1u);
                    smask[w1] &= ~hi;
                    slot = atomicAdd(&wcount, 2);
                    wlist[slot]     = w0 >> 2;
                    wlist[slot + 1] = w1 >> 2;
                }
            }
            __syncthreads();
            // ---- recompute touched chunk maxima (4 entries batched per warp) ----
            {
                int nw = wcount;   // <= 98, entries may repeat (benign)
                for (int e0 = wid; e0 < nw; e0 += 32) {
                    float        vv[4][4];
                    unsigned int mk[4][4];
                    int          cc[4];
                    #pragma unroll
                    for (int b = 0; b < 4; ++b) {
                        int e = e0 + 8 * b;
                        int c = wlist[min(e, nw - 1)];   // dup-clamped
                        cc[b] = (e < nw) ? c : -1;
                        #pragma unroll
                        for (int u = 0; u < 4; ++u) {
                            int g = c * 128 + u * 32 + lane;
                            vv[b][u] = __ldg(&dens[min(g, GTOT - 1)]);
                            mk[b][u] = smask[c * 4 + u];
                        }
                    }
                    #pragma unroll
                    for (int b = 0; b < 4; ++b) {
                        unsigned int best = 0;
                        #pragma unroll
                        for (int u = 0; u < 4; ++u) {
                            unsigned int keep = (unsigned int)(((int)(mk[b][u] << (31 - lane))) >> 31);
                            best = max(best, f2key(vv[b][u]) & keep);
                        }
                        unsigned int m = __reduce_max_sync(0xffffffffu, best);
                        if (lane == 0 && cc[b] >= 0) ckey[cc[b]] = m;
                    }
                }
            }
        }
        __syncthreads();
    }

    // ---- outputs ----
    // layout: coords_local[512*4*3] | coords_global[512*4*3] | scores[512*4] | mask[512*4]
    if (tid < KPK) {
        int k = tid;
        int n = pair >> 2;
        float nm = node_mask[n];
        int valid = pk_valid[k];
        float sc = valid ? pk_score[k] : NEGV;
        float x = 0.0f, y = 0.0f, z = 0.0f;
        if (valid) {
            int gi = pk_idx[k];
            x = grid_xyz[3 * gi + 0];
            y = grid_xyz[3 * gi + 1];
            z = grid_xyz[3 * gi + 2];
        }
        int o = (pair * KPK + k) * 3;
        out[o + 0] = x * nm;
        out[o + 1] = y * nm;
        out[o + 2] = z * nm;
        const float* R  = Rmats + n * 9;
        const float* tp = tpos + n * 3;
        float gx = R[0] * x + R[1] * y + R[2] * z + tp[0];
        float gy = R[3] * x + R[4] * y + R[5] * z + tp[1];
        float gz = R[6] * x + R[7] * y + R[8] * z + tp[2];
        out[6144 + o + 0] = gx * nm;
        out[6144 + o + 1] = gy * nm;
        out[6144 + o + 2] = gz * nm;
        out[12288 + pair * KPK + k] = sc * nm;
        out[14336 + pair * KPK + k] = (valid && nm != 0.0f) ? 1.0f : 0.0f;
    }
}

extern "C" void kernel_launch(void* const* d_in, const int* in_sizes, int n_in,
                              void* d_out, int out_size)
{
    // metadata order: density, grid_xyz, sphere_mask, coords_int, Rmats, tpos, node_mask
    const float* density   = (const float*)d_in[0];
    const float* grid_xyz  = (const float*)d_in[1];
    const float* Rmats     = (const float*)d_in[4];
    const float* tpos      = (const float*)d_in[5];
    const float* node_mask = (const float*)d_in[6];
    float* out = (float*)d_out;

    init_sphere_kernel<<<270, 256>>>(grid_xyz);          // 69120 threads -> 2160 words
    scan_kernel<<<NPAIR * 4, 256>>>(density);
    pick_kernel<<<NPAIR, 256>>>(density, grid_xyz, Rmats, tpos, node_mask, out);
}

// round 7
// speedup vs baseline: 1.0449x; 1.0449x over previous
#include <cuda_runtime.h>
#include <cuda_bf16.h>

// Problem constants
#define NXS    41
#define GTOT   68921          // 41^3
#define NX2    1681           // 41^2
#define WORDS  2154           // ceil(GTOT/32)
#define WPAD   2156           // padded word count (multiple of 4)
#define CHUNKS 539            // ceil(GTOT/128)
#define FULLCH 538            // full 128-voxel chunks
#define KPK    4
#define NEGV   (-1.0e9f)
#define VTH    (-1.0e8f)
#define NPAIR  512            // B*N*C = 1*128*4

// Global sphere bitmask (2156 words, tail zero)
__device__ unsigned int g_sphere_bits[WPAD];

// ---------------------------------------------------------------------------
// Kernel 1: sphere mask purely from index arithmetic (bit-exact vs numpy):
// xyz = float32((idx-20) * 0.3 computed in float64); norm fp32 ((x^2+y^2)+z^2)
// ---------------------------------------------------------------------------
__global__ __launch_bounds__(256) void init_sphere_kernel()
{
    int g = blockIdx.x * 256 + threadIdx.x;
    bool ok = false;
    if (g < GTOT) {
        int i = g / NX2;
        int j = (g / NXS) % NXS;
        int k = g % NXS;
        float x = (float)((double)(i - 20) * 0.3);
        float y = (float)((double)(j - 20) * 0.3);
        float z = (float)((double)(k - 20) * 0.3);
        float s = __fadd_rn(__fadd_rn(__fmul_rn(x, x), __fmul_rn(y, y)), __fmul_rn(z, z));
        ok = (__fsqrt_rn(s) <= 6.0f);
    }
    unsigned int ballot = __ballot_sync(0xffffffffu, ok);
    if ((threadIdx.x & 31) == 0) {
        int w = g >> 5;
        if (w < WPAD) g_sphere_bits[w] = ballot;
    }
}

// order-preserving float->uint key; 0 reserved as "masked" (below all real keys)
__device__ __forceinline__ unsigned int f2key(float v)
{
    int i = __float_as_int(v);
    return (unsigned int)(i ^ ((i >> 31) | 0x80000000));
}
__device__ __forceinline__ float key2f(unsigned int k)
{
    int i = (k & 0x80000000u) ? (int)(k ^ 0x80000000u) : (int)~k;
    return __int_as_float(i);
}

// ---------------------------------------------------------------------------
// Kernel 2 (fused): per-(n,c) chunk-max scan + iterative argmax + Chebyshev NMS
// ---------------------------------------------------------------------------
__global__ __launch_bounds__(256) void peaks_kernel(
    const float* __restrict__ density,   // [512, G]
    const float* __restrict__ grid_xyz,  // [G, 3]
    const float* __restrict__ Rmats,     // [128, 3, 3]
    const float* __restrict__ tpos,      // [128, 3]
    const float* __restrict__ node_mask, // [128]
    float* __restrict__ out)             // 16384 floats
{
    __shared__ uint4        smask4[CHUNKS];   // live bits, uint4 per chunk (tail padded 0)
    __shared__ unsigned int ckey[CHUNKS];     // per-chunk max (monotone key)
    __shared__ unsigned int swk[8];
    __shared__ int          sww[8];
    __shared__ float pk_score[KPK];
    __shared__ int   pk_idx[KPK];
    __shared__ int   pk_valid[KPK];
    __shared__ int   cur_i, cur_j, cur_k, cur_valid;
    __shared__ int   wlist[128];
    __shared__ int   wcount;

    unsigned int* smask = (unsigned int*)smask4;

    const int pair = blockIdx.x;            // n*4 + c
    const int tid  = threadIdx.x;
    const int lane = tid & 31;
    const int wid  = tid >> 5;
    const float* __restrict__ dens = density + (size_t)pair * GTOT;

    for (int w = tid; w < WPAD; w += 256) smask[w] = g_sphere_bits[w];
    __syncthreads();

    // ---- pass 1: per-chunk masked max; consecutive 4-chunk batches per warp,
    //      whole-batch empty skip + per-word predicated loads ----
    for (int cb = wid * 4; cb < FULLCH; cb += 32) {
        uint4 m[4];
        #pragma unroll
        for (int b = 0; b < 4; ++b) {
            int c = min(cb + b, FULLCH - 1);
            m[b] = smask4[c];
        }
        unsigned int any =
            (m[0].x | m[0].y | m[0].z | m[0].w) |
            (m[1].x | m[1].y | m[1].z | m[1].w) |
            (m[2].x | m[2].y | m[2].z | m[2].w) |
            (m[3].x | m[3].y | m[3].z | m[3].w);
        if (any == 0u) {                 // warp-uniform: whole 512-voxel batch masked
            if (lane < 4) {
                int c = cb + lane;
                if (c < FULLCH) ckey[c] = 0u;
            }
            continue;
        }
        float vv[4][4];
        #pragma unroll
        for (int b = 0; b < 4; ++b) {
            int c = min(cb + b, FULLCH - 1);
            const float* base = dens + c * 128 + lane;
            vv[b][0] = m[b].x ? __ldg(base + 0)  : 0.0f;
            vv[b][1] = m[b].y ? __ldg(base + 32) : 0.0f;
            vv[b][2] = m[b].z ? __ldg(base + 64) : 0.0f;
            vv[b][3] = m[b].w ? __ldg(base + 96) : 0.0f;
        }
        #pragma unroll
        for (int b = 0; b < 4; ++b) {
            unsigned int best = 0;
            unsigned int keep;
            keep = (unsigned int)(((int)(m[b].x << (31 - lane))) >> 31);
            best = max(best, f2key(vv[b][0]) & keep);
            keep = (unsigned int)(((int)(m[b].y << (31 - lane))) >> 31);
            best = max(best, f2key(vv[b][1]) & keep);
            keep = (unsigned int)(((int)(m[b].z << (31 - lane))) >> 31);
            best = max(best, f2key(vv[b][2]) & keep);
            keep = (unsigned int)(((int)(m[b].w << (31 - lane))) >> 31);
            best = max(best, f2key(vv[b][3]) & keep);
            unsigned int r = __reduce_max_sync(0xffffffffu, best);
            int c = cb + b;
            if (lane == 0 && c < FULLCH) ckey[c] = r;
        }
    }
    // epilogue: partial chunk 538 (warp 0, clamped addresses, padded mask bits)
    if (wid == 0) {
        uint4 m = smask4[FULLCH];
        unsigned int best = 0;
        unsigned int mw[4] = {m.x, m.y, m.z, m.w};
        #pragma unroll
        for (int u = 0; u < 4; ++u) {
            int g = FULLCH * 128 + u * 32 + lane;
            float v = mw[u] ? __ldg(&dens[min(g, GTOT - 1)]) : 0.0f;
            unsigned int keep = (unsigned int)(((int)(mw[u] << (31 - lane))) >> 31);
            best = max(best, f2key(v) & keep);
        }
        unsigned int r = __reduce_max_sync(0xffffffffu, best);
        if (lane == 0) ckey[FULLCH] = r;
    }
    __syncthreads();

    for (int t = 0; t < KPK; ++t) {
        // ---- argmax over per-chunk maxima ----
        unsigned int bk = 0;
        int bc = 0x7FFFFFFF;
        for (int c = tid; c < CHUNKS; c += 256) {
            unsigned int k = ckey[c];
            if (k > bk) { bk = k; bc = c; }     // ascending: lowest c on ties
        }
        unsigned int wm = __reduce_max_sync(0xffffffffu, bk);
        int cand = (bk == wm) ? bc : 0x7FFFFFFF;
        int wmin = (int)__reduce_min_sync(0xffffffffu, (unsigned int)cand);
        if (lane == 0) { swk[wid] = wm; sww[wid] = wmin; }
        __syncthreads();
        if (wid == 0) {
            unsigned int k8 = (lane < 8) ? swk[lane] : 0u;
            int w8 = (lane < 8) ? sww[lane] : 0x7FFFFFFF;
            unsigned int fm = __reduce_max_sync(0xffffffffu, k8);
            int c8 = (k8 == fm) ? w8 : 0x7FFFFFFF;
            int fc = (int)__reduce_min_sync(0xffffffffu, (unsigned int)c8);
            // lazy in-chunk argmax (lowest g on ties)
            unsigned int bestk = 0;
            int bestg = 0x7FFFFFFF;
            #pragma unroll
            for (int u = 0; u < 4; ++u) {
                int g = fc * 128 + u * 32 + lane;
                int gc = min(g, GTOT - 1);
                unsigned int keep = (unsigned int)(((int)(smask[fc * 4 + u] << (31 - lane))) >> 31);
                unsigned int key = f2key(__ldg(&dens[gc])) & keep;
                if (key > bestk) { bestk = key; bestg = g; }  // ascending u: lowest g
            }
            int cg = (bestk == fm) ? bestg : 0x7FFFFFFF;
            int gi = (int)__reduce_min_sync(0xffffffffu, (unsigned int)cg);
            if (lane == 0) {
                float sc = key2f(fm);
                int valid = (sc > VTH) ? 1 : 0;
                pk_score[t] = sc;
                pk_idx[t]   = gi;
                pk_valid[t] = valid;
                cur_valid = valid;
                cur_i = gi / NX2;
                cur_j = (gi / NXS) % NXS;
                cur_k = gi % NXS;
                wcount = 0;
            }
        }
        __syncthreads();

        if (t < KPK - 1 && cur_valid) {
            // ---- clear bits in <=7x7x7 Chebyshev cube; collect touched chunks ----
            int i0 = max(cur_i - 3, 0), i1 = min(cur_i + 3, NXS - 1);
            int j0 = max(cur_j - 3, 0), j1 = min(cur_j + 3, NXS - 1);
            int k0 = max(cur_k - 3, 0), k1 = min(cur_k + 3, NXS - 1);
            int nj = j1 - j0 + 1;
            int nrows = (i1 - i0 + 1) * nj;
            // rows are >=35 bits apart -> never share a 32-bit word -> no races
            if (tid < nrows) {
                int i = i0 + tid / nj;
                int j = j0 + tid % nj;
                int gb = i * NX2 + j * NXS + k0;
                int ge = gb + (k1 - k0);
                int w0 = gb >> 5, w1 = ge >> 5;
                unsigned int b0 = (unsigned int)(gb & 31);
                unsigned int b1 = (unsigned int)(ge & 31);
                unsigned int hi = (b1 == 31u) ? 0xffffffffu : ((1u << (b1 + 1)) - 1u);
                int slot;
                if (w0 == w1) {
                    unsigned int msk = hi & ~((1u << b0) - 1u);
                    smask[w0] &= ~msk;
                    slot = atomicAdd(&wcount, 1);
                    wlist[slot] = w0 >> 2;
                } else {
                    smask[w0] &= ((1u << b0) - 1u);
                    smask[w1] &= ~hi;
                    slot = atomicAdd(&wcount, 2);
                    wlist[slot]     = w0 >> 2;
                    wlist[slot + 1] = w1 >> 2;
                }
            }
            __syncthreads();
            // ---- recompute touched chunk maxima (4 entries batched per warp) ----
            {
                int nw = wcount;   // <= 98, entries may repeat (benign)
                for (int e0 = wid; e0 < nw; e0 += 32) {
                    float        vv[4][4];
                    unsigned int mk[4][4];
                    int          cc[4];
                    #pragma unroll
                    for (int b = 0; b < 4; ++b) {
                        int e = e0 + 8 * b;
                        int c = wlist[min(e, nw - 1)];   // dup-clamped
                        cc[b] = (e < nw) ? c : -1;
                        #pragma unroll
                        for (int u = 0; u < 4; ++u) {
                            int g = c * 128 + u * 32 + lane;
                            unsigned int mw = smask[c * 4 + u];
                            mk[b][u] = mw;
                            vv[b][u] = mw ? __ldg(&dens[min(g, GTOT - 1)]) : 0.0f;
                        }
                    }
                    #pragma unroll
                    for (int b = 0; b < 4; ++b) {
                        unsigned int best = 0;
                        #pragma unroll
                        for (int u = 0; u < 4; ++u) {
                            unsigned int keep = (unsigned int)(((int)(mk[b][u] << (31 - lane))) >> 31);
                            best = max(best, f2key(vv[b][u]) & keep);
                        }
                        unsigned int r = __reduce_max_sync(0xffffffffu, best);
                        if (lane == 0 && cc[b] >= 0) ckey[cc[b]] = r;
                    }
                }
            }
        }
        __syncthreads();
    }

    // ---- outputs ----
    // layout: coords_local[512*4*3] | coords_global[512*4*3] | scores[512*4] | mask[512*4]
    if (tid < KPK) {
        int k = tid;
        int n = pair >> 2;
        float nm = node_mask[n];
        int valid = pk_valid[k];
        float sc = valid ? pk_score[k] : NEGV;
        float x = 0.0f, y = 0.0f, z = 0.0f;
        if (valid) {
            int gi = pk_idx[k];
            x = grid_xyz[3 * gi + 0];
            y = grid_xyz[3 * gi + 1];
            z = grid_xyz[3 * gi + 2];
        }
        int o = (pair * KPK + k) * 3;
        out[o + 0] = x * nm;
        out[o + 1] = y * nm;
        out[o + 2] = z * nm;
        const float* R  = Rmats + n * 9;
        const float* tp = tpos + n * 3;
        float gx = R[0] * x + R[1] * y + R[2] * z + tp[0];
        float gy = R[3] * x + R[4] * y + R[5] * z + tp[1];
        float gz = R[6] * x + R[7] * y + R[8] * z + tp[2];
        out[6144 + o + 0] = gx * nm;
        out[6144 + o + 1] = gy * nm;
        out[6144 + o + 2] = gz * nm;
        out[12288 + pair * KPK + k] = sc * nm;
        out[14336 + pair * KPK + k] = (valid && nm != 0.0f) ? 1.0f : 0.0f;
    }
}

extern "C" void kernel_launch(void* const* d_in, const int* in_sizes, int n_in,
                              void* d_out, int out_size)
{
    // metadata order: density, grid_xyz, sphere_mask, coords_int, Rmats, tpos, node_mask
    const float* density   = (const float*)d_in[0];
    const float* grid_xyz  = (const float*)d_in[1];
    const float* Rmats     = (const float*)d_in[4];
    const float* tpos      = (const float*)d_in[5];
    const float* node_mask = (const float*)d_in[6];
    float* out = (float*)d_out;

    init_sphere_kernel<<<270, 256>>>();     // 69120 threads -> 2160 words
    peaks_kernel<<<NPAIR, 256>>>(density, grid_xyz, Rmats, tpos, node_mask, out);
}